// round 10
// baseline (speedup 1.0000x reference)
#include <cuda_runtime.h>
#include <math.h>

#define Bc   16
#define Cc   3
#define Rc   512
#define Ac   512
#define Gc   4096
#define Kc   4
#define NS   41     // shifts -20..+20
#define Qc   4      // 3 channels + channel-sum

// Transposed SAT layout: value SAT[r][a] stored at slice[BOFF + a*RPT + r]
#define RPT  544                 // padded row stride (a-major), 32-aligned
#define BOFF 31                  // base offset so (r+1+BOFF) is 32-aligned
#define SST  (513 * RPT + 64)    // slice stride (elements), 32-aligned

// Static scratch
__device__ float g_y[(size_t)Bc * Qc * Rc * Ac];    // row-cumsum: q=0..2 channels, q=3 chan-sum
__device__ float g_satc[(size_t)Bc * Cc * SST];     // transposed per-channel SAT
__device__ float g_sata[(size_t)Bc * SST];          // transposed channel-sum SAT
__device__ float g_w[NS];                           // w[s] = exp(-|s-20|/200), fp32

// ---- one XLA ReduceWindowRewriter(base=16) scan over 512 elems ------------
// 16-wide columns (tx), 32 tiles (t). Exact DAG: inner 16-prefix, serial
// low-half / U0 / high-half totals fold, carry apply.
__device__ __forceinline__ void scan_block16(float (&px)[16], float* dst,
                                             int t, int tx, float (*s_tot)[17])
{
    #pragma unroll
    for (int j = 1; j < 16; j++) px[j] = __fadd_rn(px[j-1], px[j]);
    s_tot[t][tx] = px[15];
    __syncthreads();

    if (t == 0) {   // threads 0..15: column tx fold
        float acc = s_tot[0][tx];                    // incT[0]
        #pragma unroll
        for (int t2 = 1; t2 < 16; t2++) {
            float T = s_tot[t2][tx];
            s_tot[t2][tx] = acc;                     // carry[t2] = incT[t2-1]
            acc = __fadd_rn(acc, T);
        }
        float U0  = acc;                             // fold of T[0..15]
        float T16 = s_tot[16][tx];
        s_tot[16][tx] = acc;                         // carry[16] = incT[15]
        float acch = T16;
        acc = __fadd_rn(U0, acch);                   // incT[16]
        #pragma unroll
        for (int t2 = 17; t2 < 32; t2++) {
            float T = s_tot[t2][tx];
            s_tot[t2][tx] = acc;                     // carry[t2] = incT[t2-1]
            acch = __fadd_rn(acch, T);
            acc = __fadd_rn(U0, acch);
        }
    }
    __syncthreads();

    const float carry = s_tot[t][tx];
    #pragma unroll
    for (int j = 0; j < 16; j++) {
        float o = (t == 0) ? px[j] : __fadd_rn(carry, px[j]);
        dst[(size_t)j * Ac] = o;
    }
    __syncthreads();   // s_tot reused by next scan
}

// ---------------- K1: fused row-axis scans, 512-thr blocks, ps in smem ------
__global__ void __launch_bounds__(512) k_rowscan(const float* __restrict__ pred)
{
    if (blockIdx.x == 0 && threadIdx.x < NS) {
        const int sh = (int)threadIdx.x - 20;
        float xw = __fdiv_rn(-(float)(sh < 0 ? -sh : sh), 200.0f);
        g_w[threadIdx.x] = (float)exp((double)xw);
    }

    const int blk  = blockIdx.x;          // 0..511
    const int acol = blk & 31;            // 32 stripes of 16 columns
    const int b    = blk >> 5;
    const int tx   = threadIdx.x & 15;
    const int t    = threadIdx.x >> 4;    // tile 0..31
    const int a    = acol * 16 + tx;

    __shared__ float s_tot[32][17];
    __shared__ float s_ps[32 * 272];      // [t][j][tx] stride 17 -> conflict-free

    const float* p  = pred + ((size_t)b * Cc * Rc) * Ac + a;
    float*       yb = g_y  + ((size_t)b * Qc * Rc) * Ac + a;
    float* psp = s_ps + t * 272 + tx;

    float px[16];
    #pragma unroll
    for (int c = 0; c < 3; c++) {
        const float* pc = p + ((size_t)c * Rc + (size_t)t * 16) * Ac;
        #pragma unroll
        for (int j = 0; j < 16; j++) px[j] = __ldg(pc + (size_t)j * Ac);
        if (c == 0) {
            #pragma unroll
            for (int j = 0; j < 16; j++) psp[j * 17] = px[j];
        } else {   // ps = (ps + v): yields ((v0+v1)+v2)
            #pragma unroll
            for (int j = 0; j < 16; j++)
                psp[j * 17] = __fadd_rn(psp[j * 17], px[j]);
        }
        scan_block16(px, yb + ((size_t)c * Rc + (size_t)t * 16) * Ac, t, tx, s_tot);
    }
    #pragma unroll
    for (int j = 0; j < 16; j++) px[j] = psp[j * 17];
    scan_block16(px, yb + ((size_t)3 * Rc + (size_t)t * 16) * Ac, t, tx, s_tot);
}

// ---------------- K2: col-axis scans -> TRANSPOSED SAT ----------------------
__global__ void __launch_bounds__(512) k_colscan()
{
    const int blk  = blockIdx.x;           // (b,q,rblk): 16*4*32
    const int rblk = blk & 31;
    const int q    = (blk >> 5) & 3;
    const int b    = blk >> 7;
    const int tid  = threadIdx.x;
    const int ty   = tid & 15;              // row in stripe
    const int t    = tid >> 4;              // a-tile 0..31

    __shared__ float s_in[16][545];
    __shared__ float s_tot[16][33];

    const float* src = g_y + (((size_t)b * Qc + q) * Rc + (size_t)rblk * 16) * Ac;

    #pragma unroll
    for (int i = 0; i < 16; i++) {
        int idx = i * 512 + tid;
        int rr = idx >> 9, cc = idx & 511;
        s_in[rr][cc + (cc >> 4)] = src[(size_t)rr * Ac + cc];
    }
    __syncthreads();

    float px[16];
    #pragma unroll
    for (int j = 0; j < 16; j++) px[j] = s_in[ty][17 * t + j];
    #pragma unroll
    for (int j = 1; j < 16; j++) px[j] = __fadd_rn(px[j-1], px[j]);
    s_tot[ty][t] = px[15];
    __syncthreads();

    if (t == 0) {
        float acc = s_tot[ty][0];
        #pragma unroll
        for (int t2 = 1; t2 < 16; t2++) {
            float T = s_tot[ty][t2];
            s_tot[ty][t2] = acc;
            acc = __fadd_rn(acc, T);
        }
        float U0  = acc;
        float T16 = s_tot[ty][16];
        s_tot[ty][16] = acc;
        float acch = T16;
        acc = __fadd_rn(U0, acch);
        #pragma unroll
        for (int t2 = 17; t2 < 32; t2++) {
            float T = s_tot[ty][t2];
            s_tot[ty][t2] = acc;
            acch = __fadd_rn(acch, T);
            acc = __fadd_rn(U0, acch);
        }
    }
    __syncthreads();

    const float carry = s_tot[ty][t];
    float* dstb = (q < 3)
        ? g_satc + (size_t)(b * Cc + q) * SST + BOFF
        : g_sata + (size_t)b * SST + BOFF;
    const int r = rblk * 16 + ty;

    #pragma unroll
    for (int j = 0; j < 16; j++) {
        float o = (t == 0) ? px[j] : __fadd_rn(carry, px[j]);
        int a = t * 16 + j;
        dstb[(size_t)(a + 1) * RPT + (r + 1)] = o;
    }

    if (rblk == 0) {
        for (int i = tid; i < 513; i += 512) {
            dstb[i] = 0.f;
            dstb[(size_t)i * RPT] = 0.f;
        }
    }
}

// ---------------- K3: per-detection vals; warp-0 epilogue -------------------
__global__ void __launch_bounds__(192) k_detect(
    const int* __restrict__ det_b, const int* __restrict__ det_c,
    const int* __restrict__ det_r, const int* __restrict__ det_a,
    const int* __restrict__ radus, const float* __restrict__ pred,
    float* __restrict__ out)
{
    const int g = blockIdx.x;
    const int t = threadIdx.x;

    __shared__ float v3[Kc][NS];

    if (t < Kc * NS) {
        const int k  = t / NS;
        const int s  = t % NS;
        const int sh = s - 20;
        const int gk = g * Kc + k;
        const int dr = det_r[gk], da = det_a[gk], db = det_b[gk];
        const int dc = det_c[gk], rad = radus[gk];

        const int rc = dr + sh;
        const int r1 = min(max(rc - rad, 0), Rc);
        const int r2 = min(max(rc + rad + 1, 0), Rc);
        const int a1 = min(max(da - 2, 0), Ac);
        const int a2 = min(max(da + 3, 0), Ac);

        const float w = g_w[s];

        const float* sc = g_satc + (size_t)(db * Cc + dc) * SST + BOFF;
        const float* sa = g_sata + (size_t)db * SST + BOFF;

        float c22 = __ldg(sc + (size_t)a2 * RPT + r2), c12 = __ldg(sc + (size_t)a2 * RPT + r1);
        float c21 = __ldg(sc + (size_t)a1 * RPT + r2), c11 = __ldg(sc + (size_t)a1 * RPT + r1);
        float rect4 = __fadd_rn(__fsub_rn(__fsub_rn(c22, c12), c21), c11);
        float val1  = __fmul_rn(rect4, w);

        float d22 = __ldg(sa + (size_t)a2 * RPT + r2), d12 = __ldg(sa + (size_t)a2 * RPT + r1);
        float d21 = __ldg(sa + (size_t)a1 * RPT + r2), d11 = __ldg(sa + (size_t)a1 * RPT + r1);
        float rect3 = __fadd_rn(__fsub_rn(__fsub_rn(d22, d12), d21), d11);
        float val2  = __fmul_rn(rect3, w);

        float val3 = __fadd_rn(__fmul_rn(0.5f, val1),
                               __fmul_rn(0.5f, __fsub_rn(val2, val1)));
        v3[k][s] = val3;
    }
    __syncthreads();

    if (t < 32) {   // warp 0 epilogue
        const int s1 = t;
        float bv;
        int   bi = s1;
        float se1 = __fadd_rn(__fadd_rn(__fadd_rn(v3[0][s1], v3[1][s1]), v3[2][s1]), v3[3][s1]);
        out[(size_t)g * NS + s1] = se1;
        bv = se1;
        const int s2 = t + 32;
        if (s2 < NS) {
            float se2 = __fadd_rn(__fadd_rn(__fadd_rn(v3[0][s2], v3[1][s2]), v3[2][s2]), v3[3][s2]);
            out[(size_t)g * NS + s2] = se2;
            if (se2 > bv) { bv = se2; bi = s2; }   // strictly greater: keep first
        }
        #pragma unroll
        for (int off = 16; off > 0; off >>= 1) {
            float ov = __shfl_xor_sync(0xffffffffu, bv, off);
            int   oi = __shfl_xor_sync(0xffffffffu, bi, off);
            if (ov > bv || (ov == bv && oi < bi)) { bv = ov; bi = oi; }
        }
        const int shift = bi - 20;

        float pmv = 0.3f;   // SMALL_PROB floor
        if (t < 12) {       // kk = t/3, c = t%3
            const int kk = t / 3, c = t % 3;
            const int gg = g * Kc + kk;
            const int rr = min(max(det_r[gg] + shift, 0), Rc - 1);
            const int db = det_b[gg], da = det_a[gg];
            pmv = fmaxf(pmv, __ldg(pred + (((size_t)db * Cc + c) * Rc + rr) * Ac + da));
        }
        #pragma unroll
        for (int off = 16; off > 0; off >>= 1)
            pmv = fmaxf(pmv, __shfl_xor_sync(0xffffffffu, pmv, off));

        if (t == 0) {
            out[(size_t)Gc * NS       + g] = (float)shift;
            out[(size_t)Gc * (NS + 1) + g] = bv;
            out[(size_t)Gc * (NS + 2) + g] = pmv;
        }
    }
}

extern "C" void kernel_launch(void* const* d_in, const int* in_sizes, int n_in,
                              void* d_out, int out_size)
{
    const float* pred  = (const float*)d_in[0];
    const int*   det_b = (const int*)  d_in[1];
    const int*   det_c = (const int*)  d_in[2];
    const int*   det_r = (const int*)  d_in[3];
    const int*   det_a = (const int*)  d_in[4];
    const int*   radus = (const int*)  d_in[5];
    float*       out   = (float*)d_out;

    k_rowscan<<<Bc * (Ac / 16), 512>>>(pred);         // 512 blocks, ps in smem
    k_colscan<<<Bc * Qc * 32, 512>>>();               // 16-row stripes
    k_detect<<<Gc, 192>>>(det_b, det_c, det_r, det_a, radus, pred, out);
}